// round 1
// baseline (speedup 1.0000x reference)
#include <cuda_runtime.h>

#define BB 32
#define SS 2048
#define DD 1024
#define EE 16
#define KK 4
#define OO 1024
#define KD 4096
#define BS (BB*SS)

// ---------------- scratch (static device memory is allowed) ----------------
__device__ float g_logits[BB*EE*SS];          // [b][e][s]   4 MB
__device__ int   g_tidx[BB*EE*KK];
__device__ float g_tval[BB*EE*KK];
__device__ float g_inp[(size_t)BB*EE*KD];     // [b][e][k*D] 8 MB
__device__ float g_h1[BB*EE*OO];              // 2 MB
__device__ float g_h2[BB*EE*OO];              // 2 MB

// ---------------- f32x2 helpers (Blackwell FFMA2 via PTX) ----------------
union F2 { unsigned long long u; float2 f; };

__device__ __forceinline__ void ffma2(F2& acc, const F2& a, const F2& b) {
    asm("fma.rn.f32x2 %0, %1, %2, %0;" : "+l"(acc.u) : "l"(a.u), "l"(b.u));
}
__device__ __forceinline__ F2 fpack(float lo, float hi) {
    F2 r;
    asm("mov.b64 %0, {%1, %2};"
        : "=l"(r.u) : "r"(__float_as_uint(lo)), "r"(__float_as_uint(hi)));
    return r;
}

// ---------------- K1: gate logits  logits[b][e][s] = x[b,s,:] . Wg[:,e] ---
// block = 128 threads = 4 warps; warp w handles experts [4w,4w+4) for the
// block's 128 tokens. Wg held in registers as f32x2 pairs over d. x is read
// coalesced (LDG.64); the 4 warps share each x row through L1.
__global__ __launch_bounds__(128) void k1_logits(const float* __restrict__ x,
                                                 const float* __restrict__ Wg) {
    const int lane = threadIdx.x & 31;
    const int eg   = threadIdx.x >> 5;       // expert group 0..3
    const int tok0 = blockIdx.x * 128;

    F2 wreg[16][4];                          // 128 regs: Wg pairs over d
#pragma unroll
    for (int c = 0; c < 16; c++) {
        const int d = (c * 32 + lane) * 2;
#pragma unroll
        for (int j = 0; j < 4; j++) {
            const int e = eg * 4 + j;
            wreg[c][j] = fpack(Wg[d * EE + e], Wg[(d + 1) * EE + e]);
        }
    }

    for (int t = 0; t < 128; t++) {
        const int token = tok0 + t;
        const float2* xr = (const float2*)(x + (size_t)token * DD);
        F2 a0, a1, a2, a3;
        a0.u = a1.u = a2.u = a3.u = 0ull;
#pragma unroll
        for (int c = 0; c < 16; c++) {
            F2 xv; xv.f = xr[c * 32 + lane];
            ffma2(a0, xv, wreg[c][0]);
            ffma2(a1, xv, wreg[c][1]);
            ffma2(a2, xv, wreg[c][2]);
            ffma2(a3, xv, wreg[c][3]);
        }
        float r0 = a0.f.x + a0.f.y;
        float r1 = a1.f.x + a1.f.y;
        float r2 = a2.f.x + a2.f.y;
        float r3 = a3.f.x + a3.f.y;
#pragma unroll
        for (int off = 16; off; off >>= 1) {
            r0 += __shfl_xor_sync(0xffffffffu, r0, off);
            r1 += __shfl_xor_sync(0xffffffffu, r1, off);
            r2 += __shfl_xor_sync(0xffffffffu, r2, off);
            r3 += __shfl_xor_sync(0xffffffffu, r3, off);
        }
        if (lane < 4) {
            const float rv = (lane == 0) ? r0 : (lane == 1) ? r1 : (lane == 2) ? r2 : r3;
            const int b = token >> 11;
            const int s = token & (SS - 1);
            g_logits[((size_t)(b * EE + eg * 4 + lane)) * SS + s] = rv;
        }
    }
}

// ---------------- K2: per-(b,e) softmax stats + top-4 --------------------
// one warp per (b,e). softmax is over tokens (axis S); top-k(probs) ==
// top-k(logits). vals = exp(l-max)/sumexp. bg cancels in the softmax.
__global__ void k2_topk() {
    const int pair = blockIdx.x * 8 + (threadIdx.x >> 5);   // b*16+e
    const int lane = threadIdx.x & 31;
    const float* __restrict__ L = g_logits + (size_t)pair * SS;

    float m = -3.402823466e38f;
    for (int s = lane; s < SS; s += 32) m = fmaxf(m, L[s]);
#pragma unroll
    for (int off = 16; off; off >>= 1) m = fmaxf(m, __shfl_xor_sync(0xffffffffu, m, off));

    int sel0 = -1, sel1 = -1, sel2 = -1, sel3 = -1;
    float sv0 = 0.f, sv1 = 0.f, sv2 = 0.f, sv3 = 0.f;
#pragma unroll
    for (int j = 0; j < 4; j++) {
        float bv = -3.402823466e38f;
        int bi = SS;
        for (int s = lane; s < SS; s += 32) {
            if (s == sel0 || s == sel1 || s == sel2) continue;
            const float v = L[s];
            if (v > bv) { bv = v; bi = s; }   // ascending scan keeps lowest index on ties
        }
#pragma unroll
        for (int off = 16; off; off >>= 1) {
            const float ov = __shfl_xor_sync(0xffffffffu, bv, off);
            const int   oi = __shfl_xor_sync(0xffffffffu, bi, off);
            if (ov > bv || (ov == bv && oi < bi)) { bv = ov; bi = oi; }
        }
        if (j == 0)      { sel0 = bi; sv0 = bv; }
        else if (j == 1) { sel1 = bi; sv1 = bv; }
        else if (j == 2) { sel2 = bi; sv2 = bv; }
        else             { sel3 = bi; sv3 = bv; }
    }

    float sum = 0.f;
    for (int s = lane; s < SS; s += 32) sum += expf(L[s] - m);
#pragma unroll
    for (int off = 16; off; off >>= 1) sum += __shfl_xor_sync(0xffffffffu, sum, off);

    if (lane == 0) {
        const float inv = 1.0f / sum;
        g_tidx[pair * 4 + 0] = sel0; g_tval[pair * 4 + 0] = expf(sv0 - m) * inv;
        g_tidx[pair * 4 + 1] = sel1; g_tval[pair * 4 + 1] = expf(sv1 - m) * inv;
        g_tidx[pair * 4 + 2] = sel2; g_tval[pair * 4 + 2] = expf(sv2 - m) * inv;
        g_tidx[pair * 4 + 3] = sel3; g_tval[pair * 4 + 3] = expf(sv3 - m) * inv;
    }
}

// ---------------- K3: gather+scale the selected tokens -------------------
// one block per (b,e,k): inp[b][e][k*D+d] = x[b, idx, d] * val
__global__ void k3_gather(const float* __restrict__ x) {
    const int p  = blockIdx.x;            // ((b*16+e)*4 + k)
    const int k  = p & 3;
    const int be = p >> 2;
    const int b  = p >> 6;
    const int idx = g_tidx[p];
    const float val = g_tval[p];
    const float4* src = (const float4*)(x + ((size_t)b * SS + idx) * DD);
    float4* dst = (float4*)(g_inp + (size_t)be * KD + k * DD);
    const float4 v = src[threadIdx.x];
    dst[threadIdx.x] = make_float4(v.x * val, v.y * val, v.z * val, v.w * val);
}

// ---------------- grouped GEMM: out[32,1024] = A[32,KDIM] x W[e][KDIM,1024]
// grid (8 otiles, 16 experts), 512 threads: 4-way in-block K-split x 128 cols.
// Each thread holds all 32 rows as 16 f32x2 accumulators; A tile staged
// transposed in smem (pad 34 -> conflict-free LDS.64 row-pairs); W streamed
// coalesced. Epilogue reduces the 4 K-quarters through smem (deterministic).
template <int KDIM>
__global__ __launch_bounds__(512) void gemm_kernel(const float* __restrict__ A,
                                                   const float* __restrict__ W,
                                                   const float* __restrict__ bias,
                                                   float* __restrict__ Out,
                                                   int doRelu) {
    constexpr int KQ = KDIM / 4;
    __shared__ __align__(16) float As[4 * 32 * 34];   // also reused as 4x8x128 red buf
    const int tid = threadIdx.x;
    const int qh  = tid >> 7;         // K-quarter 0..3
    const int col = tid & 127;
    const int e   = blockIdx.y;
    const int oc  = blockIdx.x * 128 + col;
    const float* Ae = A + (size_t)e * KDIM;                       // row m at +m*(16*KDIM)
    const float* Wp = W + ((size_t)e * KDIM + qh * KQ) * OO + oc;

    F2 acc[16];
#pragma unroll
    for (int i = 0; i < 16; i++) acc[i].u = 0ull;

    for (int kc = 0; kc < KQ; kc += 32) {
        __syncthreads();
#pragma unroll
        for (int r = 0; r < 8; r++) {
            const int combo = (tid >> 5) + 16 * r;   // 0..127 = (quarter, row)
            const int h  = combo >> 5;
            const int mm = combo & 31;
            const int j  = tid & 31;
            As[(h * 32 + j) * 34 + mm] =
                Ae[(size_t)mm * (EE * KDIM) + h * KQ + kc + j];
        }
        __syncthreads();
#pragma unroll 8
        for (int j = 0; j < 32; j++) {
            const float w = Wp[(size_t)(kc + j) * OO];
            const F2 w2 = fpack(w, w);
            const float2* ap = (const float2*)(As + (qh * 32 + j) * 34);
#pragma unroll
            for (int i = 0; i < 16; i++) {
                F2 a; a.f = ap[i];
                ffma2(acc[i], a, w2);
            }
        }
    }

    // epilogue: reduce 4 quarters, add bias, optional relu, store [B][E][O]
#pragma unroll
    for (int g = 0; g < 4; g++) {
        __syncthreads();
#pragma unroll
        for (int i = 0; i < 4; i++) {
            As[qh * 1024 + (2 * i)     * 128 + col] = acc[g * 4 + i].f.x;
            As[qh * 1024 + (2 * i + 1) * 128 + col] = acc[g * 4 + i].f.y;
        }
        __syncthreads();
#pragma unroll
        for (int t = 0; t < 2; t++) {
            const int idx = tid + t * 512;            // 0..1023 = ml*128+c
            const int ml = idx >> 7;
            const int c  = idx & 127;
            float s = As[idx] + As[1024 + idx] + As[2048 + idx] + As[3072 + idx];
            s += bias[e * OO + blockIdx.x * 128 + c];
            if (doRelu) s = fmaxf(s, 0.f);
            Out[((size_t)(g * 8 + ml) * EE + e) * OO + blockIdx.x * 128 + c] = s;
        }
    }
}

// ---------------- launch ----------------
extern "C" void kernel_launch(void* const* d_in, const int* in_sizes, int n_in,
                              void* d_out, int out_size) {
    const float* x  = (const float*)d_in[0];
    const float* Wg = (const float*)d_in[1];
    // d_in[2] = bg: constant over the softmax (token) axis -> cancels exactly.
    const float* W1 = (const float*)d_in[3];
    const float* b1 = (const float*)d_in[4];
    const float* W2 = (const float*)d_in[5];
    const float* b2 = (const float*)d_in[6];
    const float* W3 = (const float*)d_in[7];
    const float* b3 = (const float*)d_in[8];
    float* out = (float*)d_out;

    void *pInp = nullptr, *pH1 = nullptr, *pH2 = nullptr;
    cudaGetSymbolAddress(&pInp, g_inp);
    cudaGetSymbolAddress(&pH1,  g_h1);
    cudaGetSymbolAddress(&pH2,  g_h2);

    k1_logits<<<BS / 128, 128>>>(x, Wg);
    k2_topk<<<(BB * EE) / 8, 256>>>();
    k3_gather<<<BB * EE * KK, 256>>>(x);
    gemm_kernel<KD><<<dim3(8, EE), 512>>>((const float*)pInp, W1, b1, (float*)pH1, 1);
    gemm_kernel<OO><<<dim3(8, EE), 512>>>((const float*)pH1,  W2, b2, (float*)pH2, 1);
    gemm_kernel<OO><<<dim3(8, EE), 512>>>((const float*)pH2,  W3, b3, out, 0);
}

// round 2
// speedup vs baseline: 1.6401x; 1.6401x over previous
#include <cuda_runtime.h>

#define BB 32
#define SS 2048
#define DD 1024
#define EE 16
#define KK 4
#define OO 1024
#define KD 4096
#define BS (BB*SS)

// ---------------- scratch ----------------
__device__ float g_logits[BB*EE*SS];          // [b][e][s]   4 MB
__device__ int   g_tidx[BB*EE*KK];
__device__ float g_tval[BB*EE*KK];
__device__ float g_inp[(size_t)BB*EE*KD];     // [b][e][k*D] 8 MB
__device__ float g_h1[BB*EE*OO];              // 2 MB
__device__ float g_h2[BB*EE*OO];              // 2 MB

// ---------------- f32x2 helpers ----------------
union F2 { unsigned long long u; float2 f; };

__device__ __forceinline__ void ffma2(F2& acc, const F2& a, const F2& b) {
    asm("fma.rn.f32x2 %0, %1, %2, %0;" : "+l"(acc.u) : "l"(a.u), "l"(b.u));
}
__device__ __forceinline__ F2 fsplat(float v) {
    F2 r;
    asm("mov.b64 %0, {%1, %1};" : "=l"(r.u) : "r"(__float_as_uint(v)));
    return r;
}

// ---------------- K1: gate logits -----------------------------------------
// logits[b][e][s] = x[b,s,:] . Wg[:,e]
// Block 256 thr, 512 tokens/block (2 per thread, t and t+256). Per 16-d
// chunk: x tile row-cached in smem (coalesced LDG.128 -> LDS.64 pitch-18,
// conflict-free), Wg chunk transposed into smem and read as BROADCAST
// LDS.64 shared across both tokens. No cross-lane reductions at all.
__global__ __launch_bounds__(256) void k1_logits(const float* __restrict__ x,
                                                 const float* __restrict__ Wg) {
    __shared__ float xs[512 * 18];        // token-major, pitch 18 (36.9KB)
    __shared__ float wt[16 * 18];         // WgT chunk [e][16d], pitch 18
    const int tid  = threadIdx.x;
    const int tok0 = blockIdx.x * 512;

    F2 acc[32];                            // [e][token 0/1]
#pragma unroll
    for (int i = 0; i < 32; i++) acc[i].u = 0ull;

    for (int dc = 0; dc < 64; dc++) {
        __syncthreads();
        // stage x chunk: 512 tokens x 16 d
#pragma unroll
        for (int i = 0; i < 8; i++) {
            const int g   = tid + 256 * i;        // 0..2047
            const int tok = g >> 2;
            const int c4  = (g & 3) * 4;
            const float4 v = *(const float4*)(x + (size_t)(tok0 + tok) * DD + dc * 16 + c4);
            F2* dst = (F2*)(xs + tok * 18 + c4);
            F2 p0; p0.f = make_float2(v.x, v.y);
            F2 p1; p1.f = make_float2(v.z, v.w);
            dst[0] = p0; dst[1] = p1;
        }
        // stage Wg chunk transposed: wt[e][d] for d in chunk
        {
            const int e  = tid & 15;
            const int dd = tid >> 4;       // 0..15
            wt[e * 18 + dd] = Wg[(dc * 16 + dd) * EE + e];
        }
        __syncthreads();

        const F2* a0p = (const F2*)(xs + tid * 18);
        const F2* a1p = (const F2*)(xs + (tid + 256) * 18);
#pragma unroll
        for (int dp = 0; dp < 8; dp++) {
            const F2 a0 = a0p[dp];
            const F2 a1 = a1p[dp];
#pragma unroll
            for (int e = 0; e < 16; e++) {
                const F2 b = ((const F2*)(wt + e * 18))[dp];   // broadcast
                ffma2(acc[e * 2 + 0], a0, b);
                ffma2(acc[e * 2 + 1], a1, b);
            }
        }
    }

    const int t0 = tok0 + tid;
    const int t1 = t0 + 256;
    const int b  = t0 >> 11;               // 512 | 2048 so both tokens same b
    const int s0 = t0 & (SS - 1);
    const int s1 = t1 & (SS - 1);
#pragma unroll
    for (int e = 0; e < 16; e++) {
        g_logits[((size_t)(b * EE + e)) * SS + s0] = acc[e * 2 + 0].f.x + acc[e * 2 + 0].f.y;
        g_logits[((size_t)(b * EE + e)) * SS + s1] = acc[e * 2 + 1].f.x + acc[e * 2 + 1].f.y;
    }
}

// ---------------- K2: per-(b,e) softmax stats + top-4 --------------------
__global__ void k2_topk() {
    const int pair = blockIdx.x * 8 + (threadIdx.x >> 5);   // b*16+e
    const int lane = threadIdx.x & 31;
    const float* __restrict__ L = g_logits + (size_t)pair * SS;

    float m = -3.402823466e38f;
    for (int s = lane; s < SS; s += 32) m = fmaxf(m, L[s]);
#pragma unroll
    for (int off = 16; off; off >>= 1) m = fmaxf(m, __shfl_xor_sync(0xffffffffu, m, off));

    int sel0 = -1, sel1 = -1, sel2 = -1, sel3 = -1;
    float sv0 = 0.f, sv1 = 0.f, sv2 = 0.f, sv3 = 0.f;
#pragma unroll
    for (int j = 0; j < 4; j++) {
        float bv = -3.402823466e38f;
        int bi = SS;
        for (int s = lane; s < SS; s += 32) {
            if (s == sel0 || s == sel1 || s == sel2) continue;
            const float v = L[s];
            if (v > bv) { bv = v; bi = s; }
        }
#pragma unroll
        for (int off = 16; off; off >>= 1) {
            const float ov = __shfl_xor_sync(0xffffffffu, bv, off);
            const int   oi = __shfl_xor_sync(0xffffffffu, bi, off);
            if (ov > bv || (ov == bv && oi < bi)) { bv = ov; bi = oi; }
        }
        if (j == 0)      { sel0 = bi; sv0 = bv; }
        else if (j == 1) { sel1 = bi; sv1 = bv; }
        else if (j == 2) { sel2 = bi; sv2 = bv; }
        else             { sel3 = bi; sv3 = bv; }
    }

    float sum = 0.f;
    for (int s = lane; s < SS; s += 32) sum += expf(L[s] - m);
#pragma unroll
    for (int off = 16; off; off >>= 1) sum += __shfl_xor_sync(0xffffffffu, sum, off);

    if (lane == 0) {
        const float inv = 1.0f / sum;
        g_tidx[pair * 4 + 0] = sel0; g_tval[pair * 4 + 0] = expf(sv0 - m) * inv;
        g_tidx[pair * 4 + 1] = sel1; g_tval[pair * 4 + 1] = expf(sv1 - m) * inv;
        g_tidx[pair * 4 + 2] = sel2; g_tval[pair * 4 + 2] = expf(sv2 - m) * inv;
        g_tidx[pair * 4 + 3] = sel3; g_tval[pair * 4 + 3] = expf(sv3 - m) * inv;
    }
}

// ---------------- K3: gather+scale ---------------------------------------
__global__ void k3_gather(const float* __restrict__ x) {
    const int p  = blockIdx.x;            // ((b*16+e)*4 + k)
    const int k  = p & 3;
    const int be = p >> 2;
    const int b  = p >> 6;
    const int idx = g_tidx[p];
    const float val = g_tval[p];
    const float4* src = (const float4*)(x + ((size_t)b * SS + idx) * DD);
    float4* dst = (float4*)(g_inp + (size_t)be * KD + k * DD);
    const float4 v = src[threadIdx.x];
    dst[threadIdx.x] = make_float4(v.x * val, v.y * val, v.z * val, v.w * val);
}

// ---------------- grouped GEMM -------------------------------------------
// Out[32,1024] = A[32,KDIM] x W[e][KDIM,1024]  (+bias, optional relu)
// grid (8 otiles, 16 experts), 512 thr = 16 warps:
//   warp w: rg = w&1 (16-row group), ks = w>>1 (8-way K split)
//   lane: 4 adjacent cols (lane*4..+3)  -> W via LDG.128
// Thread tile 16 rows x 4 cols; acc = 8 row-pair F2 x 4 cols = 32 F2.
// Per k-step: 8 broadcast LDS.64 (A row pairs) + 1 LDG.128 (W) + 4 splats
// + 32 FFMA2  -> FMA-pipe bound.
template <int KDIM>
__global__ __launch_bounds__(512) void gemm_kernel(const float* __restrict__ A,
                                                   const float* __restrict__ W,
                                                   const float* __restrict__ bias,
                                                   float* __restrict__ Out,
                                                   int doRelu) {
    constexpr int KPS = KDIM / 8;                 // per-warp K slice
    __shared__ __align__(16) float As[256 * 34];  // [kk 0..255][row 0..31] pad34 (34.8KB)
    const int tid  = threadIdx.x;
    const int lane = tid & 31;
    const int w    = tid >> 5;
    const int rg   = w & 1;
    const int ks   = w >> 1;
    const int e    = blockIdx.y;
    const int oc   = blockIdx.x * 128 + lane * 4;
    const float* Ae = A + (size_t)e * KDIM;       // row m at +m*(EE*KDIM)
    const float* Wp = W + ((size_t)e * KDIM + ks * KPS) * OO + oc;

    F2 acc[32];                                   // [rp 0..7][c 0..3]
#pragma unroll
    for (int i = 0; i < 32; i++) acc[i].u = 0ull;

    for (int kc = 0; kc < KPS; kc += 32) {
        __syncthreads();
        // stage 8 x 32 k x 32 rows, transposed to [kk][row]
#pragma unroll
        for (int i = 0; i < 4; i++) {
            const int g4  = tid + 512 * i;        // 0..2047
            const int row = g4 >> 6;              // 0..31
            const int kk4 = (g4 & 63) * 4;        // 0..252
            const int ks2 = kk4 >> 5;
            const int kin = kk4 & 31;
            const float4 v = *(const float4*)(Ae + (size_t)row * (EE * KDIM)
                                              + ks2 * KPS + kc + kin);
            As[(kk4 + 0) * 34 + row] = v.x;
            As[(kk4 + 1) * 34 + row] = v.y;
            As[(kk4 + 2) * 34 + row] = v.z;
            As[(kk4 + 3) * 34 + row] = v.w;
        }
        __syncthreads();

#pragma unroll 4
        for (int j = 0; j < 32; j++) {
            const float4 w4 = *(const float4*)(Wp + (size_t)(kc + j) * OO);
            const F2 b0 = fsplat(w4.x), b1 = fsplat(w4.y),
                     b2 = fsplat(w4.z), b3 = fsplat(w4.w);
            const F2* ar = (const F2*)(As + (ks * 32 + j) * 34 + rg * 16);
#pragma unroll
            for (int rp = 0; rp < 8; rp++) {
                const F2 a = ar[rp];               // broadcast within warp
                ffma2(acc[rp * 4 + 0], a, b0);
                ffma2(acc[rp * 4 + 1], a, b1);
                ffma2(acc[rp * 4 + 2], a, b2);
                ffma2(acc[rp * 4 + 3], a, b3);
            }
        }
    }

    // epilogue: reduce 8 K-slices via smem, bias (+relu), store
    F2* buf = (F2*)As;                             // 2048 F2 = 16KB
#pragma unroll
    for (int rp = 0; rp < 8; rp++) {
        __syncthreads();
#pragma unroll
        for (int c = 0; c < 4; c++)
            buf[((ks * 2 + rg) * 32 + lane) * 4 + c] = acc[rp * 4 + c];
        __syncthreads();
        if (tid < 256) {
            const int rrg = tid >> 7;
            const int col = tid & 127;
            const int li  = col >> 2;
            const int ci  = col & 3;
            float sx = 0.f, sy = 0.f;
#pragma unroll
            for (int kss = 0; kss < 8; kss++) {
                const F2 v = buf[((kss * 2 + rrg) * 32 + li) * 4 + ci];
                sx += v.f.x; sy += v.f.y;
            }
            const int occol = blockIdx.x * 128 + col;
            const float bv = bias[e * OO + occol];
            sx += bv; sy += bv;
            if (doRelu) { sx = fmaxf(sx, 0.f); sy = fmaxf(sy, 0.f); }
            const int r0 = rrg * 16 + 2 * rp;
            Out[((size_t)r0 * EE + e) * OO + occol] = sx;
            Out[((size_t)(r0 + 1) * EE + e) * OO + occol] = sy;
        }
    }
}

// ---------------- launch ----------------
extern "C" void kernel_launch(void* const* d_in, const int* in_sizes, int n_in,
                              void* d_out, int out_size) {
    const float* x  = (const float*)d_in[0];
    const float* Wg = (const float*)d_in[1];
    // d_in[2] = bg: constant over the softmax (token) axis -> cancels exactly.
    const float* W1 = (const float*)d_in[3];
    const float* b1 = (const float*)d_in[4];
    const float* W2 = (const float*)d_in[5];
    const float* b2 = (const float*)d_in[6];
    const float* W3 = (const float*)d_in[7];
    const float* b3 = (const float*)d_in[8];
    float* out = (float*)d_out;

    void *pInp = nullptr, *pH1 = nullptr, *pH2 = nullptr;
    cudaGetSymbolAddress(&pInp, g_inp);
    cudaGetSymbolAddress(&pH1,  g_h1);
    cudaGetSymbolAddress(&pH2,  g_h2);

    k1_logits<<<BS / 512, 256>>>(x, Wg);
    k2_topk<<<(BB * EE) / 8, 256>>>();
    k3_gather<<<BB * EE * KK, 256>>>(x);
    gemm_kernel<KD><<<dim3(8, EE), 512>>>((const float*)pInp, W1, b1, (float*)pH1, 1);
    gemm_kernel<OO><<<dim3(8, EE), 512>>>((const float*)pH1,  W2, b2, (float*)pH2, 1);
    gemm_kernel<OO><<<dim3(8, EE), 512>>>((const float*)pH2,  W3, b3, out, 0);
}

// round 3
// speedup vs baseline: 2.3182x; 1.4135x over previous
#include <cuda_runtime.h>

#define BB 32
#define SS 2048
#define DD 1024
#define EE 16
#define KK 4
#define OO 1024
#define KD 4096
#define BS (BB*SS)

// ---------------- scratch ----------------
__device__ float g_logits[BB*EE*SS];          // [b][e][s]   4 MB
__device__ int   g_tidx[BB*EE*KK];
__device__ float g_tval[BB*EE*KK];
__device__ float g_inp[(size_t)BB*EE*KD];     // [b][e][k*D] 8 MB
__device__ float g_h1[BB*EE*OO];              // 2 MB
__device__ float g_h2[BB*EE*OO];              // 2 MB

// ---------------- f32x2 helpers ----------------
union F2 { unsigned long long u; float2 f; };

__device__ __forceinline__ void ffma2(F2& acc, const F2& a, const F2& b) {
    asm("fma.rn.f32x2 %0, %1, %2, %0;" : "+l"(acc.u) : "l"(a.u), "l"(b.u));
}
__device__ __forceinline__ F2 fsplat(float v) {
    F2 r;
    asm("mov.b64 %0, {%1, %1};" : "=l"(r.u) : "r"(__float_as_uint(v)));
    return r;
}

// ---------------- K1: gate logits -----------------------------------------
__global__ __launch_bounds__(256) void k1_logits(const float* __restrict__ x,
                                                 const float* __restrict__ Wg) {
    __shared__ float xs[512 * 18];        // token-major, pitch 18
    __shared__ float wt[16 * 18];         // WgT chunk [e][16d]
    const int tid  = threadIdx.x;
    const int tok0 = blockIdx.x * 512;

    F2 acc[32];
#pragma unroll
    for (int i = 0; i < 32; i++) acc[i].u = 0ull;

    for (int dc = 0; dc < 64; dc++) {
        __syncthreads();
#pragma unroll
        for (int i = 0; i < 8; i++) {
            const int g   = tid + 256 * i;
            const int tok = g >> 2;
            const int c4  = (g & 3) * 4;
            const float4 v = *(const float4*)(x + (size_t)(tok0 + tok) * DD + dc * 16 + c4);
            F2* dst = (F2*)(xs + tok * 18 + c4);
            F2 p0; p0.f = make_float2(v.x, v.y);
            F2 p1; p1.f = make_float2(v.z, v.w);
            dst[0] = p0; dst[1] = p1;
        }
        {
            const int e  = tid & 15;
            const int dd = tid >> 4;
            wt[e * 18 + dd] = Wg[(dc * 16 + dd) * EE + e];
        }
        __syncthreads();

        const F2* a0p = (const F2*)(xs + tid * 18);
        const F2* a1p = (const F2*)(xs + (tid + 256) * 18);
#pragma unroll
        for (int dp = 0; dp < 8; dp++) {
            const F2 a0 = a0p[dp];
            const F2 a1 = a1p[dp];
#pragma unroll
            for (int e = 0; e < 16; e++) {
                const F2 b = ((const F2*)(wt + e * 18))[dp];
                ffma2(acc[e * 2 + 0], a0, b);
                ffma2(acc[e * 2 + 1], a1, b);
            }
        }
    }

    const int t0 = tok0 + tid;
    const int t1 = t0 + 256;
    const int b  = t0 >> 11;
    const int s0 = t0 & (SS - 1);
    const int s1 = t1 & (SS - 1);
#pragma unroll
    for (int e = 0; e < 16; e++) {
        g_logits[((size_t)(b * EE + e)) * SS + s0] = acc[e * 2 + 0].f.x + acc[e * 2 + 0].f.y;
        g_logits[((size_t)(b * EE + e)) * SS + s1] = acc[e * 2 + 1].f.x + acc[e * 2 + 1].f.y;
    }
}

// ---------------- K2: per-(b,e) softmax stats + top-4 --------------------
__global__ void k2_topk() {
    const int pair = blockIdx.x * 8 + (threadIdx.x >> 5);
    const int lane = threadIdx.x & 31;
    const float* __restrict__ L = g_logits + (size_t)pair * SS;

    float m = -3.402823466e38f;
    for (int s = lane; s < SS; s += 32) m = fmaxf(m, L[s]);
#pragma unroll
    for (int off = 16; off; off >>= 1) m = fmaxf(m, __shfl_xor_sync(0xffffffffu, m, off));

    int sel0 = -1, sel1 = -1, sel2 = -1, sel3 = -1;
    float sv0 = 0.f, sv1 = 0.f, sv2 = 0.f, sv3 = 0.f;
#pragma unroll
    for (int j = 0; j < 4; j++) {
        float bv = -3.402823466e38f;
        int bi = SS;
        for (int s = lane; s < SS; s += 32) {
            if (s == sel0 || s == sel1 || s == sel2) continue;
            const float v = L[s];
            if (v > bv) { bv = v; bi = s; }
        }
#pragma unroll
        for (int off = 16; off; off >>= 1) {
            const float ov = __shfl_xor_sync(0xffffffffu, bv, off);
            const int   oi = __shfl_xor_sync(0xffffffffu, bi, off);
            if (ov > bv || (ov == bv && oi < bi)) { bv = ov; bi = oi; }
        }
        if (j == 0)      { sel0 = bi; sv0 = bv; }
        else if (j == 1) { sel1 = bi; sv1 = bv; }
        else if (j == 2) { sel2 = bi; sv2 = bv; }
        else             { sel3 = bi; sv3 = bv; }
    }

    float sum = 0.f;
    for (int s = lane; s < SS; s += 32) sum += expf(L[s] - m);
#pragma unroll
    for (int off = 16; off; off >>= 1) sum += __shfl_xor_sync(0xffffffffu, sum, off);

    if (lane == 0) {
        const float inv = 1.0f / sum;
        g_tidx[pair * 4 + 0] = sel0; g_tval[pair * 4 + 0] = expf(sv0 - m) * inv;
        g_tidx[pair * 4 + 1] = sel1; g_tval[pair * 4 + 1] = expf(sv1 - m) * inv;
        g_tidx[pair * 4 + 2] = sel2; g_tval[pair * 4 + 2] = expf(sv2 - m) * inv;
        g_tidx[pair * 4 + 3] = sel3; g_tval[pair * 4 + 3] = expf(sv3 - m) * inv;
    }
}

// ---------------- K3: gather+scale ---------------------------------------
__global__ void k3_gather(const float* __restrict__ x) {
    const int p  = blockIdx.x;
    const int k  = p & 3;
    const int be = p >> 2;
    const int b  = p >> 6;
    const int idx = g_tidx[p];
    const float val = g_tval[p];
    const float4* src = (const float4*)(x + ((size_t)b * SS + idx) * DD);
    float4* dst = (float4*)(g_inp + (size_t)be * KD + k * DD);
    const float4 v = src[threadIdx.x];
    dst[threadIdx.x] = make_float4(v.x * val, v.y * val, v.z * val, v.w * val);
}

// ---------------- grouped GEMM -------------------------------------------
// Out[32,1024] = A[32,KDIM] x W[e][KDIM,1024]  (+bias, optional relu)
// grid (8 otiles, 16 experts), 512 thr = 16 warps:
//   warp w: rg = w&1 (16-row group), ks = w>>1 (8-way K split)
//   lane: 4 adjacent cols -> W via LDG.128.
// Inner loop software-pipelined: W rows prefetched in double-buffered
// register groups of 4 (distance ~4*64 fma-cyc > DRAM latency); first group
// of each chunk issued BEFORE the A-staging barriers so the LDG pipeline
// never drains.
template <int KDIM>
__global__ __launch_bounds__(512) void gemm_kernel(const float* __restrict__ A,
                                                   const float* __restrict__ W,
                                                   const float* __restrict__ bias,
                                                   float* __restrict__ Out,
                                                   int doRelu) {
    constexpr int KPS = KDIM / 8;
    __shared__ __align__(16) float As[256 * 34];
    const int tid  = threadIdx.x;
    const int lane = tid & 31;
    const int w    = tid >> 5;
    const int rg   = w & 1;
    const int ks   = w >> 1;
    const int e    = blockIdx.y;
    const int oc   = blockIdx.x * 128 + lane * 4;
    const float* Ae = A + (size_t)e * KDIM;
    const float* Wp = W + ((size_t)e * KDIM + ks * KPS) * OO + oc;

    F2 acc[32];
#pragma unroll
    for (int i = 0; i < 32; i++) acc[i].u = 0ull;

    float4 wbufA[4], wbufB[4];

    for (int kc = 0; kc < KPS; kc += 32) {
        const float* Wk = Wp + (size_t)kc * OO;
        // issue first W group before barriers: overlaps with A staging
#pragma unroll
        for (int t = 0; t < 4; t++)
            wbufA[t] = *(const float4*)(Wk + (size_t)t * OO);

        __syncthreads();
#pragma unroll
        for (int i = 0; i < 4; i++) {
            const int g4  = tid + 512 * i;
            const int row = g4 >> 6;
            const int kk4 = (g4 & 63) * 4;
            const int ks2 = kk4 >> 5;
            const int kin = kk4 & 31;
            const float4 v = *(const float4*)(Ae + (size_t)row * (EE * KDIM)
                                              + ks2 * KPS + kc + kin);
            As[(kk4 + 0) * 34 + row] = v.x;
            As[(kk4 + 1) * 34 + row] = v.y;
            As[(kk4 + 2) * 34 + row] = v.z;
            As[(kk4 + 3) * 34 + row] = v.w;
        }
        __syncthreads();

#pragma unroll
        for (int jg = 0; jg < 8; jg++) {
            const bool useA = (jg & 1) == 0;
            if (jg < 7) {
                const float* p = Wk + (size_t)((jg + 1) * 4) * OO;
#pragma unroll
                for (int t = 0; t < 4; t++) {
                    const float4 v = *(const float4*)(p + (size_t)t * OO);
                    if (useA) wbufB[t] = v; else wbufA[t] = v;
                }
            }
#pragma unroll
            for (int jj = 0; jj < 4; jj++) {
                const float4 q = useA ? wbufA[jj] : wbufB[jj];
                const F2 b0 = fsplat(q.x), b1 = fsplat(q.y),
                         b2 = fsplat(q.z), b3 = fsplat(q.w);
                const F2* ar = (const F2*)(As + (ks * 32 + jg * 4 + jj) * 34 + rg * 16);
#pragma unroll
                for (int rp = 0; rp < 8; rp++) {
                    const F2 a = ar[rp];
                    ffma2(acc[rp * 4 + 0], a, b0);
                    ffma2(acc[rp * 4 + 1], a, b1);
                    ffma2(acc[rp * 4 + 2], a, b2);
                    ffma2(acc[rp * 4 + 3], a, b3);
                }
            }
        }
    }

    // epilogue: reduce 8 K-slices via smem, bias (+relu), store
    F2* buf = (F2*)As;
#pragma unroll
    for (int rp = 0; rp < 8; rp++) {
        __syncthreads();
#pragma unroll
        for (int c = 0; c < 4; c++)
            buf[((ks * 2 + rg) * 32 + lane) * 4 + c] = acc[rp * 4 + c];
        __syncthreads();
        if (tid < 256) {
            const int rrg = tid >> 7;
            const int col = tid & 127;
            const int li  = col >> 2;
            const int ci  = col & 3;
            float sx = 0.f, sy = 0.f;
#pragma unroll
            for (int kss = 0; kss < 8; kss++) {
                const F2 v = buf[((kss * 2 + rrg) * 32 + li) * 4 + ci];
                sx += v.f.x; sy += v.f.y;
            }
            const int occol = blockIdx.x * 128 + col;
            const float bv = bias[e * OO + occol];
            sx += bv; sy += bv;
            if (doRelu) { sx = fmaxf(sx, 0.f); sy = fmaxf(sy, 0.f); }
            const int r0 = rrg * 16 + 2 * rp;
            Out[((size_t)r0 * EE + e) * OO + occol] = sx;
            Out[((size_t)(r0 + 1) * EE + e) * OO + occol] = sy;
        }
    }
}

// ---------------- launch ----------------
extern "C" void kernel_launch(void* const* d_in, const int* in_sizes, int n_in,
                              void* d_out, int out_size) {
    const float* x  = (const float*)d_in[0];
    const float* Wg = (const float*)d_in[1];
    // d_in[2] = bg: constant over the softmax (token) axis -> cancels exactly.
    const float* W1 = (const float*)d_in[3];
    const float* b1 = (const float*)d_in[4];
    const float* W2 = (const float*)d_in[5];
    const float* b2 = (const float*)d_in[6];
    const float* W3 = (const float*)d_in[7];
    const float* b3 = (const float*)d_in[8];
    float* out = (float*)d_out;

    void *pInp = nullptr, *pH1 = nullptr, *pH2 = nullptr;
    cudaGetSymbolAddress(&pInp, g_inp);
    cudaGetSymbolAddress(&pH1,  g_h1);
    cudaGetSymbolAddress(&pH2,  g_h2);

    k1_logits<<<BS / 512, 256>>>(x, Wg);
    k2_topk<<<(BB * EE) / 8, 256>>>();
    k3_gather<<<BB * EE * KK, 256>>>(x);
    gemm_kernel<KD><<<dim3(8, EE), 512>>>((const float*)pInp, W1, b1, (float*)pH1, 1);
    gemm_kernel<OO><<<dim3(8, EE), 512>>>((const float*)pH1,  W2, b2, (float*)pH2, 1);
    gemm_kernel<OO><<<dim3(8, EE), 512>>>((const float*)pH2,  W3, b3, out, 0);
}